// round 10
// baseline (speedup 1.0000x reference)
#include <cuda_runtime.h>
#include <cstdint>

#define NRES 320
#define CDIM 128
#define NH 4
#define DH 32
#define NN (NRES*NRES)
#define AP 132   // padded row stride for MMA smem tiles

// ---------- tf32 mma helpers ----------
__device__ __forceinline__ uint32_t f2tf(float f) {
    uint32_t u; asm("cvt.rna.tf32.f32 %0, %1;" : "=r"(u) : "f"(f)); return u;
}
__device__ __forceinline__ void mma_tf32(float* d,
    uint32_t a0, uint32_t a1, uint32_t a2, uint32_t a3,
    uint32_t b0, uint32_t b1)
{
    asm volatile(
        "mma.sync.aligned.m16n8k8.row.col.f32.tf32.tf32.f32 "
        "{%0,%1,%2,%3}, {%4,%5,%6,%7}, {%8,%9}, {%0,%1,%2,%3};"
        : "+f"(d[0]), "+f"(d[1]), "+f"(d[2]), "+f"(d[3])
        : "r"(a0), "r"(a1), "r"(a2), "r"(a3), "r"(b0), "r"(b1));
}

// -------- device scratch --------
__device__ float g_q   [(size_t)NRES*NH*NRES*DH];   // [i][h][j][d]
__device__ float g_k   [(size_t)NRES*NH*NRES*DH];
__device__ float g_v   [(size_t)NRES*NH*NRES*DH];
__device__ float g_gate[(size_t)NRES*NH*NRES*DH];
__device__ float g_og  [(size_t)NN*CDIM];
__device__ float g_bias[(size_t)NH*NN];             // [h][q][j]
__device__ uint32_t g_wt[5*128*128];                // transposed tf32 weights [s][n][k]

// =====================================================================
// Kernel W: one-shot transpose+convert of the 5 weight matrices.
// =====================================================================
__global__ __launch_bounds__(256, 4) void kW(
    const float* __restrict__ wq, const float* __restrict__ wk,
    const float* __restrict__ wv, const float* __restrict__ wg,
    const float* __restrict__ wo)
{
    int idx = blockIdx.x * 256 + threadIdx.x;    // 5*16384 total
    int s = idx >> 14, r = idx & 16383;
    int n = r >> 7, k = r & 127;
    const float* W = (s == 0) ? wq : (s == 1) ? wk : (s == 2) ? wv
                   : (s == 3) ? wg : wo;
    g_wt[idx] = f2tf(W[k * 128 + n]);
}

// =====================================================================
// Kernel A (tensor, 1024 thr): LN + q/k/v/gate projections + tri bias.
// (unchanged from R9)
// =====================================================================
#define KA_AHI 0
#define KA_ALO (KA_AHI + 128*AP)
#define KA_WT  (KA_ALO + 128*AP)
#define KA_SG  (KA_WT  + 128*AP)
#define KA_SB  (KA_SG + 128)
#define KA_WB  (KA_SB + 128)
#define SMEM_A ((KA_WB + 512) * 4)

__global__ __launch_bounds__(1024, 1) void kA(
    const float* __restrict__ x,   const float* __restrict__ lng,
    const float* __restrict__ lnb, const float* __restrict__ wb,
    const float* __restrict__ bg)
{
    extern __shared__ float sm[];
    float* ahi_f = sm + KA_AHI;
    float* alo_f = sm + KA_ALO;
    float* sg    = sm + KA_SG;
    float* sb    = sm + KA_SB;
    float* wbs   = sm + KA_WB;
    uint32_t* ahi = (uint32_t*)ahi_f;
    uint32_t* alo = (uint32_t*)alo_f;
    uint32_t* wt  = (uint32_t*)(sm + KA_WT);

    int tid = threadIdx.x, lane = tid & 31, w = tid >> 5;
    int g2 = lane >> 2, cq = lane & 3;
    int rw = w & 7, nc = w >> 3;
    int colbase = nc * 32;
    int Rb = blockIdx.x * 128;

    if (tid < 128) { sg[tid] = lng[tid]; sb[tid] = lnb[tid]; }
    if (tid >= 128 && tid < 640) wbs[tid - 128] = wb[tid - 128];

    // ---- layernorm: 8 threads per row (16 elems each) ----
    int row = tid >> 3, sub = tid & 7;
    float xv[16];
    const float* xr = x + (size_t)(Rb + row) * CDIM + sub * 16;
    #pragma unroll
    for (int m4 = 0; m4 < 4; m4++) {
        float4 t = *(const float4*)(xr + m4 * 4);
        xv[m4*4+0] = t.x; xv[m4*4+1] = t.y; xv[m4*4+2] = t.z; xv[m4*4+3] = t.w;
    }
    float sum = 0.f, sq = 0.f;
    #pragma unroll
    for (int m = 0; m < 16; m++) { sum += xv[m]; sq += xv[m]*xv[m]; }
    #pragma unroll
    for (int off = 4; off >= 1; off >>= 1) {
        sum += __shfl_xor_sync(0xffffffffu, sum, off, 8);
        sq  += __shfl_xor_sync(0xffffffffu, sq,  off, 8);
    }
    float mu = sum * (1.f / CDIM);
    float rs = rsqrtf(sq * (1.f / CDIM) - mu * mu + 1e-5f);

    __syncthreads();   // sg/sb/wbs ready
    #pragma unroll
    for (int m = 0; m < 16; m++) {
        int c = sub * 16 + m;
        float val = (xv[m] - mu) * rs * sg[c] + sb[c];
        uint32_t hb = f2tf(val);
        ahi[row * AP + c] = hb;
        alo[row * AP + c] = f2tf(val - __uint_as_float(hb));
    }
    __syncthreads();   // A ready

    // ---- triangle bias: 512 items on first 512 threads ----
    if (tid < 512) {
        int r = tid >> 2, h2 = tid & 3;
        float acc = 0.f;
        #pragma unroll 8
        for (int kk = 0; kk < CDIM; kk++)
            acc += (ahi_f[r * AP + kk] + alo_f[r * AP + kk]) * wbs[kk * NH + h2];
        g_bias[(size_t)h2 * NN + Rb + r] = acc;
    }

    // ---- 4 projection chunks ----
    int r0 = (rw << 4) + g2;
    int R0 = Rb + r0, R1 = R0 + 8;
    int i0 = R0 / NRES, j0 = R0 - i0 * NRES;
    int i1 = R1 / NRES, j1 = R1 - i1 * NRES;

    #pragma unroll 1
    for (int s = 0; s < 4; s++) {
        const uint4* src = (const uint4*)(g_wt + s * 16384);
        #pragma unroll
        for (int i = 0; i < 4; i++) {
            int idx4 = tid + i * 1024;
            int n = idx4 >> 5, k4 = idx4 & 31;
            uint4 vv = __ldg(&src[idx4]);
            *(uint4*)&wt[n * AP + k4 * 4] = vv;
        }
        __syncthreads();

        float acc[4][4];
        #pragma unroll
        for (int t = 0; t < 4; t++)
            #pragma unroll
            for (int e = 0; e < 4; e++) acc[t][e] = 0.f;

        #pragma unroll 4
        for (int ks = 0; ks < 16; ks++) {
            int kc = ks * 8;
            uint32_t h0 = ahi[r0 * AP + kc + cq];
            uint32_t h1 = ahi[(r0 + 8) * AP + kc + cq];
            uint32_t h2_ = ahi[r0 * AP + kc + cq + 4];
            uint32_t h3 = ahi[(r0 + 8) * AP + kc + cq + 4];
            uint32_t l0 = alo[r0 * AP + kc + cq];
            uint32_t l1 = alo[(r0 + 8) * AP + kc + cq];
            uint32_t l2 = alo[r0 * AP + kc + cq + 4];
            uint32_t l3 = alo[(r0 + 8) * AP + kc + cq + 4];
            #pragma unroll
            for (int t = 0; t < 4; t++) {
                int n0 = (colbase + t * 8 + g2) * AP + kc;
                uint32_t b0 = wt[n0 + cq];
                uint32_t b1 = wt[n0 + cq + 4];
                mma_tf32(acc[t], h0, h1, h2_, h3, b0, b1);
                mma_tf32(acc[t], l0, l1, l2, l3, b0, b1);
            }
        }

        if (s == 0) {
            #pragma unroll
            for (int t = 0; t < 4; t++)
                #pragma unroll
                for (int e = 0; e < 4; e++) acc[t][e] *= 0.17677669529663687f;
        }
        if (s == 3) {
            #pragma unroll
            for (int t = 0; t < 4; t++) {
                int col = colbase + t * 8 + cq * 2;
                float2 bgv = __ldg((const float2*)&bg[col]);
                acc[t][0] = 1.f / (1.f + __expf(-(acc[t][0] + bgv.x)));
                acc[t][1] = 1.f / (1.f + __expf(-(acc[t][1] + bgv.y)));
                acc[t][2] = 1.f / (1.f + __expf(-(acc[t][2] + bgv.x)));
                acc[t][3] = 1.f / (1.f + __expf(-(acc[t][3] + bgv.y)));
            }
        }
        float* dst = (s == 0) ? g_q : (s == 1) ? g_k : (s == 2) ? g_v : g_gate;
        #pragma unroll
        for (int t = 0; t < 4; t++) {
            int col = colbase + t * 8 + cq * 2;
            int h = col >> 5, d = col & 31;
            *(float2*)&dst[(((size_t)i0 * NH + h) * NRES + j0) * DH + d] =
                make_float2(acc[t][0], acc[t][1]);
            *(float2*)&dst[(((size_t)i1 * NH + h) * NRES + j1) * DH + d] =
                make_float2(acc[t][2], acc[t][3]);
        }
        __syncthreads();
    }
}

// =====================================================================
// Kernel B: attention per (i,h), tf32 mma, 256 thr, TWO blocks/SM.
// P relayout via shuffles (no smem P), Q fragments direct from global.
// =====================================================================
#define KS_OFF    0
#define VS_OFF    (KS_OFF + 320*36)
#define MSK_OFF   (VS_OFF + 320*36)
#define RED_OFF   (MSK_OFF + 320)              // 8 warps x 16 rows x {m,s}
#define OPART_OFF (RED_OFF + 8*16*2)           // 4 pairs x [16][32]
#define SMEM_B    ((OPART_OFF + 4*16*32) * 4)

__global__ __launch_bounds__(256, 2) void kB(const float* __restrict__ mask)
{
    extern __shared__ float sm[];
    uint32_t* ksu = (uint32_t*)(sm + KS_OFF);
    uint32_t* vsu = (uint32_t*)(sm + VS_OFF);
    float* msk   = sm + MSK_OFF;
    float* red   = sm + RED_OFF;
    float* opart = sm + OPART_OFF;

    int i = blockIdx.x, h = blockIdx.y;
    int tid = threadIdx.x, lane = tid & 31, w = tid >> 5;
    int p2 = w >> 1, half = w & 1;
    int khalf = half * 160;
    int g = lane >> 2, c = lane & 3;

    size_t base = ((size_t)i * NH + h) * (NRES * DH);
    const float* kg = g_k    + base;
    const float* qg = g_q    + base;
    const float* vg = g_v    + base;
    const float* gg = g_gate + base;

    for (int idx = tid; idx < NRES * DH; idx += 256) {
        int kk = idx >> 5, d = idx & 31;
        ksu[kk * 36 + d] = f2tf(kg[idx]);
        vsu[kk * 36 + d] = f2tf(vg[idx]);
    }
    for (int idx = tid; idx < NRES; idx += 256)
        msk[idx] = 1.0e9f * (mask[(size_t)i * NRES + idx] - 1.f);

    const float* bias_h = g_bias + (size_t)h * NN;

    int src_lo = (lane & 0x1c) | (c >> 1);
    int src_hi = src_lo + 2;
    bool odd = (c & 1) != 0;

    __syncthreads();

    #pragma unroll 1
    for (int p = 0; p < 5; p++) {
        int qbase = p * 64 + p2 * 16;

        // ---- S = Q_tile x K_half^T : Q fragments direct from global ----
        float s[20][4];
        #pragma unroll
        for (int t = 0; t < 20; t++)
            #pragma unroll
            for (int e = 0; e < 4; e++) s[t][e] = 0.f;

        #pragma unroll
        for (int ds = 0; ds < 4; ds++) {
            int dc = ds * 8;
            const float* q0 = &qg[(qbase + g) * DH + dc];
            const float* q1 = &qg[(qbase + g + 8) * DH + dc];
            uint32_t a0 = f2tf(__ldg(q0 + c));
            uint32_t a1 = f2tf(__ldg(q1 + c));
            uint32_t a2 = f2tf(__ldg(q0 + c + 4));
            uint32_t a3 = f2tf(__ldg(q1 + c + 4));
            #pragma unroll
            for (int t = 0; t < 20; t++) {
                int n0 = (khalf + t * 8 + g) * 36 + dc;
                uint32_t b0 = ksu[n0 + c];
                uint32_t b1 = ksu[n0 + c + 4];
                mma_tf32(s[t], a0, a1, a2, a3, b0, b1);
            }
        }

        int row0 = qbase + g, row1 = row0 + 8;
        #pragma unroll
        for (int t = 0; t < 20; t++) {
            int col = khalf + t * 8 + c * 2;
            float2 mk = *(const float2*)&msk[col];
            float2 bA = __ldg((const float2*)&bias_h[(size_t)row0 * NRES + col]);
            float2 bB = __ldg((const float2*)&bias_h[(size_t)row1 * NRES + col]);
            s[t][0] += bA.x + mk.x;  s[t][1] += bA.y + mk.y;
            s[t][2] += bB.x + mk.x;  s[t][3] += bB.y + mk.y;
        }

        // ---- local softmax over 160 ----
        float mA = -1e30f, mB = -1e30f;
        #pragma unroll
        for (int t = 0; t < 20; t++) {
            mA = fmaxf(mA, fmaxf(s[t][0], s[t][1]));
            mB = fmaxf(mB, fmaxf(s[t][2], s[t][3]));
        }
        mA = fmaxf(mA, __shfl_xor_sync(0xffffffffu, mA, 1));
        mB = fmaxf(mB, __shfl_xor_sync(0xffffffffu, mB, 1));
        mA = fmaxf(mA, __shfl_xor_sync(0xffffffffu, mA, 2));
        mB = fmaxf(mB, __shfl_xor_sync(0xffffffffu, mB, 2));

        float sA = 0.f, sB = 0.f;
        #pragma unroll
        for (int t = 0; t < 20; t++) {
            s[t][0] = __expf(s[t][0] - mA); sA += s[t][0];
            s[t][1] = __expf(s[t][1] - mA); sA += s[t][1];
            s[t][2] = __expf(s[t][2] - mB); sB += s[t][2];
            s[t][3] = __expf(s[t][3] - mB); sB += s[t][3];
        }
        sA += __shfl_xor_sync(0xffffffffu, sA, 1);
        sB += __shfl_xor_sync(0xffffffffu, sB, 1);
        sA += __shfl_xor_sync(0xffffffffu, sA, 2);
        sB += __shfl_xor_sync(0xffffffffu, sB, 2);

        if (c == 0) {
            red[(w * 16 + g)     * 2]     = mA;
            red[(w * 16 + g)     * 2 + 1] = sA;
            red[(w * 16 + g + 8) * 2]     = mB;
            red[(w * 16 + g + 8) * 2 + 1] = sB;
        }
        __syncthreads();

        // ---- merge with partner half ----
        int wo = w ^ 1;
        float moA = red[(wo * 16 + g) * 2],     soA = red[(wo * 16 + g) * 2 + 1];
        float moB = red[(wo * 16 + g + 8) * 2], soB = red[(wo * 16 + g + 8) * 2 + 1];
        float MA = fmaxf(mA, moA), MB = fmaxf(mB, moB);
        float eA = __expf(mA - MA), eB = __expf(mB - MB);
        float facA = eA / (sA * eA + soA * __expf(moA - MA));
        float facB = eB / (sB * eB + soB * __expf(moB - MB));

        #pragma unroll
        for (int t = 0; t < 20; t++) {
            s[t][0] *= facA; s[t][1] *= facA;
            s[t][2] *= facB; s[t][3] *= facB;
        }

        // ---- O = P x V_half : P fragments via shuffles ----
        float o[4][4];
        #pragma unroll
        for (int t = 0; t < 4; t++)
            #pragma unroll
            for (int e = 0; e < 4; e++) o[t][e] = 0.f;

        #pragma unroll 4
        for (int ks = 0; ks < 20; ks++) {
            float u0 = __shfl_sync(0xffffffffu, s[ks][0], src_lo);
            float u1 = __shfl_sync(0xffffffffu, s[ks][1], src_lo);
            float w0 = __shfl_sync(0xffffffffu, s[ks][2], src_lo);
            float w1 = __shfl_sync(0xffffffffu, s[ks][3], src_lo);
            float y0 = __shfl_sync(0xffffffffu, s[ks][0], src_hi);
            float y1 = __shfl_sync(0xffffffffu, s[ks][1], src_hi);
            float z0 = __shfl_sync(0xffffffffu, s[ks][2], src_hi);
            float z1 = __shfl_sync(0xffffffffu, s[ks][3], src_hi);
            uint32_t a0 = f2tf(odd ? u1 : u0);
            uint32_t a1 = f2tf(odd ? w1 : w0);
            uint32_t a2 = f2tf(odd ? y1 : y0);
            uint32_t a3 = f2tf(odd ? z1 : z0);
            int kc = ks * 8;
            int vr0 = (khalf + kc + c) * 36;
            int vr1 = (khalf + kc + c + 4) * 36;
            #pragma unroll
            for (int t = 0; t < 4; t++) {
                uint32_t b0 = vsu[vr0 + t * 8 + g];
                uint32_t b1 = vsu[vr1 + t * 8 + g];
                mma_tf32(o[t], a0, a1, a2, a3, b0, b1);
            }
        }

        // ---- pair merge + gate + store ----
        if (half) {
            #pragma unroll
            for (int t = 0; t < 4; t++) {
                int col = t * 8 + c * 2;
                *(float2*)&opart[(p2 * 16 + g) * 32 + col]     = make_float2(o[t][0], o[t][1]);
                *(float2*)&opart[(p2 * 16 + g + 8) * 32 + col] = make_float2(o[t][2], o[t][3]);
            }
        }
        __syncthreads();
        if (!half) {
            #pragma unroll
            for (int t = 0; t < 4; t++) {
                int col = t * 8 + c * 2;
                float2 qa = *(const float2*)&opart[(p2 * 16 + g) * 32 + col];
                float2 qb = *(const float2*)&opart[(p2 * 16 + g + 8) * 32 + col];
                float2 gA = __ldg((const float2*)&gg[row0 * 32 + col]);
                float2 gB = __ldg((const float2*)&gg[row1 * 32 + col]);
                float2 rA = make_float2((o[t][0] + qa.x) * gA.x, (o[t][1] + qa.y) * gA.y);
                float2 rB = make_float2((o[t][2] + qb.x) * gB.x, (o[t][3] + qb.y) * gB.y);
                *(float2*)&g_og[((size_t)i * NRES + row0) * CDIM + h * DH + col] = rA;
                *(float2*)&g_og[((size_t)i * NRES + row1) * CDIM + h * DH + col] = rB;
            }
        }
        __syncthreads();
    }
}

// =====================================================================
// Kernel C (tensor, 1024 thr): out = og @ wo + bo. (unchanged from R9)
// =====================================================================
#define KC_A  0
#define KC_WT (KC_A + 128*AP)
#define SMEM_C ((KC_WT + 128*AP) * 4)

__global__ __launch_bounds__(1024, 1) void kC(
    const float* __restrict__ bo, float* __restrict__ out)
{
    extern __shared__ float sm[];
    uint32_t* ao = (uint32_t*)(sm + KC_A);
    uint32_t* wt = (uint32_t*)(sm + KC_WT);

    int tid = threadIdx.x, lane = tid & 31, w = tid >> 5;
    int g2 = lane >> 2, cq = lane & 3;
    int rw = w & 7, nc = w >> 3;
    int colbase = nc * 32;
    int Rb = blockIdx.x * 128;

    const uint4* wsrc = (const uint4*)(g_wt + 4 * 16384);
    const float4* asrc = (const float4*)(g_og + (size_t)Rb * CDIM);
    #pragma unroll
    for (int i = 0; i < 4; i++) {
        int idx4 = tid + i * 1024;
        int n = idx4 >> 5, k4 = idx4 & 31;
        uint4 wv = __ldg(&wsrc[idx4]);
        *(uint4*)&wt[n * AP + k4 * 4] = wv;
        float4 av = asrc[idx4];
        uint4 at;
        at.x = f2tf(av.x); at.y = f2tf(av.y); at.z = f2tf(av.z); at.w = f2tf(av.w);
        *(uint4*)&ao[n * AP + k4 * 4] = at;
    }
    __syncthreads();

    int r0 = (rw << 4) + g2;

    float acc[4][4];
    #pragma unroll
    for (int t = 0; t < 4; t++)
        #pragma unroll
        for (int e = 0; e < 4; e++) acc[t][e] = 0.f;

    #pragma unroll 4
    for (int ks = 0; ks < 16; ks++) {
        int kc = ks * 8;
        uint32_t a0 = ao[r0 * AP + kc + cq];
        uint32_t a1 = ao[(r0 + 8) * AP + kc + cq];
        uint32_t a2 = ao[r0 * AP + kc + cq + 4];
        uint32_t a3 = ao[(r0 + 8) * AP + kc + cq + 4];
        #pragma unroll
        for (int t = 0; t < 4; t++) {
            int n0 = (colbase + t * 8 + g2) * AP + kc;
            uint32_t b0 = wt[n0 + cq];
            uint32_t b1 = wt[n0 + cq + 4];
            mma_tf32(acc[t], a0, a1, a2, a3, b0, b1);
        }
    }

    #pragma unroll
    for (int t = 0; t < 4; t++) {
        int col = colbase + t * 8 + cq * 2;
        float2 bb = __ldg((const float2*)&bo[col]);
        *(float2*)&out[(size_t)(Rb + r0) * CDIM + col] =
            make_float2(acc[t][0] + bb.x, acc[t][1] + bb.y);
        *(float2*)&out[(size_t)(Rb + r0 + 8) * CDIM + col] =
            make_float2(acc[t][2] + bb.x, acc[t][3] + bb.y);
    }
}

// =====================================================================
extern "C" void kernel_launch(void* const* d_in, const int* in_sizes, int n_in,
                              void* d_out, int out_size)
{
    const float* x    = (const float*)d_in[0];
    const float* mask = (const float*)d_in[1];
    const float* lng  = (const float*)d_in[2];
    const float* lnb  = (const float*)d_in[3];
    const float* wb   = (const float*)d_in[4];
    const float* wq   = (const float*)d_in[5];
    const float* wk   = (const float*)d_in[6];
    const float* wv   = (const float*)d_in[7];
    const float* wg   = (const float*)d_in[8];
    const float* bg   = (const float*)d_in[9];
    const float* wo   = (const float*)d_in[10];
    const float* bo   = (const float*)d_in[11];
    float* out = (float*)d_out;

    cudaFuncSetAttribute(kA, cudaFuncAttributeMaxDynamicSharedMemorySize, SMEM_A);
    cudaFuncSetAttribute(kB, cudaFuncAttributeMaxDynamicSharedMemorySize, SMEM_B);
    cudaFuncSetAttribute(kC, cudaFuncAttributeMaxDynamicSharedMemorySize, SMEM_C);

    kW<<<320, 256>>>(wq, wk, wv, wg, wo);
    kA<<<NN / 128, 1024, SMEM_A>>>(x, lng, lnb, wb, bg);
    kB<<<dim3(NRES, NH), 256, SMEM_B>>>(mask);
    kC<<<NN / 128, 1024, SMEM_C>>>(bo, out);
}

// round 11
// speedup vs baseline: 1.8286x; 1.8286x over previous
#include <cuda_runtime.h>
#include <cstdint>

#define NRES 320
#define CDIM 128
#define NH 4
#define DH 32
#define NN (NRES*NRES)
#define AP 132   // padded row stride for MMA smem tiles

// ---------- tf32 mma helpers ----------
__device__ __forceinline__ uint32_t f2tf(float f) {
    uint32_t u; asm("cvt.rna.tf32.f32 %0, %1;" : "=r"(u) : "f"(f)); return u;
}
__device__ __forceinline__ void mma_tf32(float* d,
    uint32_t a0, uint32_t a1, uint32_t a2, uint32_t a3,
    uint32_t b0, uint32_t b1)
{
    asm volatile(
        "mma.sync.aligned.m16n8k8.row.col.f32.tf32.tf32.f32 "
        "{%0,%1,%2,%3}, {%4,%5,%6,%7}, {%8,%9}, {%0,%1,%2,%3};"
        : "+f"(d[0]), "+f"(d[1]), "+f"(d[2]), "+f"(d[3])
        : "r"(a0), "r"(a1), "r"(a2), "r"(a3), "r"(b0), "r"(b1));
}

// -------- device scratch --------
__device__ float g_q   [(size_t)NRES*NH*NRES*DH];   // [i][h][j][d]
__device__ float g_k   [(size_t)NRES*NH*NRES*DH];
__device__ float g_v   [(size_t)NRES*NH*NRES*DH];
__device__ float g_gate[(size_t)NRES*NH*NRES*DH];
__device__ float g_og  [(size_t)NN*CDIM];
__device__ float g_bias[(size_t)NH*NN];             // [h][q][j]
__device__ uint32_t g_wt[5*128*128];                // transposed tf32 weights [s][n][k]

// =====================================================================
// Kernel W: one-shot transpose+convert of the 5 weight matrices.
// =====================================================================
__global__ __launch_bounds__(256, 4) void kW(
    const float* __restrict__ wq, const float* __restrict__ wk,
    const float* __restrict__ wv, const float* __restrict__ wg,
    const float* __restrict__ wo)
{
    int idx = blockIdx.x * 256 + threadIdx.x;    // 5*16384 total
    int s = idx >> 14, r = idx & 16383;
    int n = r >> 7, k = r & 127;
    const float* W = (s == 0) ? wq : (s == 1) ? wk : (s == 2) ? wv
                   : (s == 3) ? wg : wo;
    g_wt[idx] = f2tf(W[k * 128 + n]);
}

// =====================================================================
// Kernel A (tensor, 1024 thr): LN + q/k/v/gate projections + tri bias.
// Split-A (hi+lo) for q/k/v; single-term for gate (sigmoid-tolerant).
// =====================================================================
#define KA_AHI 0
#define KA_ALO (KA_AHI + 128*AP)
#define KA_WT  (KA_ALO + 128*AP)
#define KA_SG  (KA_WT  + 128*AP)
#define KA_SB  (KA_SG + 128)
#define KA_WB  (KA_SB + 128)
#define SMEM_A ((KA_WB + 512) * 4)

__global__ __launch_bounds__(1024, 1) void kA(
    const float* __restrict__ x,   const float* __restrict__ lng,
    const float* __restrict__ lnb, const float* __restrict__ wb,
    const float* __restrict__ bg)
{
    extern __shared__ float sm[];
    float* ahi_f = sm + KA_AHI;
    float* alo_f = sm + KA_ALO;
    float* sg    = sm + KA_SG;
    float* sb    = sm + KA_SB;
    float* wbs   = sm + KA_WB;
    uint32_t* ahi = (uint32_t*)ahi_f;
    uint32_t* alo = (uint32_t*)alo_f;
    uint32_t* wt  = (uint32_t*)(sm + KA_WT);

    int tid = threadIdx.x, lane = tid & 31, w = tid >> 5;
    int g2 = lane >> 2, cq = lane & 3;
    int rw = w & 7, nc = w >> 3;
    int colbase = nc * 32;
    int Rb = blockIdx.x * 128;

    if (tid < 128) { sg[tid] = lng[tid]; sb[tid] = lnb[tid]; }
    if (tid >= 128 && tid < 640) wbs[tid - 128] = wb[tid - 128];

    // ---- layernorm: 8 threads per row (16 elems each) ----
    int row = tid >> 3, sub = tid & 7;
    float xv[16];
    const float* xr = x + (size_t)(Rb + row) * CDIM + sub * 16;
    #pragma unroll
    for (int m4 = 0; m4 < 4; m4++) {
        float4 t = *(const float4*)(xr + m4 * 4);
        xv[m4*4+0] = t.x; xv[m4*4+1] = t.y; xv[m4*4+2] = t.z; xv[m4*4+3] = t.w;
    }
    float sum = 0.f, sq = 0.f;
    #pragma unroll
    for (int m = 0; m < 16; m++) { sum += xv[m]; sq += xv[m]*xv[m]; }
    #pragma unroll
    for (int off = 4; off >= 1; off >>= 1) {
        sum += __shfl_xor_sync(0xffffffffu, sum, off, 8);
        sq  += __shfl_xor_sync(0xffffffffu, sq,  off, 8);
    }
    float mu = sum * (1.f / CDIM);
    float rs = rsqrtf(sq * (1.f / CDIM) - mu * mu + 1e-5f);

    __syncthreads();   // sg/sb/wbs ready
    #pragma unroll
    for (int m = 0; m < 16; m++) {
        int c = sub * 16 + m;
        float val = (xv[m] - mu) * rs * sg[c] + sb[c];
        uint32_t hb = f2tf(val);
        ahi[row * AP + c] = hb;
        alo[row * AP + c] = f2tf(val - __uint_as_float(hb));
    }
    __syncthreads();   // A ready

    // ---- triangle bias: 512 items on first 512 threads ----
    if (tid < 512) {
        int r = tid >> 2, h2 = tid & 3;
        float acc = 0.f;
        #pragma unroll 8
        for (int kk = 0; kk < CDIM; kk++)
            acc += (ahi_f[r * AP + kk] + alo_f[r * AP + kk]) * wbs[kk * NH + h2];
        g_bias[(size_t)h2 * NN + Rb + r] = acc;
    }

    // ---- 4 projection chunks ----
    int r0 = (rw << 4) + g2;
    int R0 = Rb + r0, R1 = R0 + 8;
    int i0 = R0 / NRES, j0 = R0 - i0 * NRES;
    int i1 = R1 / NRES, j1 = R1 - i1 * NRES;

    #pragma unroll 1
    for (int s = 0; s < 4; s++) {
        const uint4* src = (const uint4*)(g_wt + s * 16384);
        #pragma unroll
        for (int i = 0; i < 4; i++) {
            int idx4 = tid + i * 1024;
            int n = idx4 >> 5, k4 = idx4 & 31;
            uint4 vv = __ldg(&src[idx4]);
            *(uint4*)&wt[n * AP + k4 * 4] = vv;
        }
        __syncthreads();

        float acc[4][4];
        #pragma unroll
        for (int t = 0; t < 4; t++)
            #pragma unroll
            for (int e = 0; e < 4; e++) acc[t][e] = 0.f;

        #pragma unroll 4
        for (int ks = 0; ks < 16; ks++) {
            int kc = ks * 8;
            uint32_t h0 = ahi[r0 * AP + kc + cq];
            uint32_t h1 = ahi[(r0 + 8) * AP + kc + cq];
            uint32_t h2_ = ahi[r0 * AP + kc + cq + 4];
            uint32_t h3 = ahi[(r0 + 8) * AP + kc + cq + 4];
            if (s != 3) {
                uint32_t l0 = alo[r0 * AP + kc + cq];
                uint32_t l1 = alo[(r0 + 8) * AP + kc + cq];
                uint32_t l2 = alo[r0 * AP + kc + cq + 4];
                uint32_t l3 = alo[(r0 + 8) * AP + kc + cq + 4];
                #pragma unroll
                for (int t = 0; t < 4; t++) {
                    int n0 = (colbase + t * 8 + g2) * AP + kc;
                    uint32_t b0 = wt[n0 + cq];
                    uint32_t b1 = wt[n0 + cq + 4];
                    mma_tf32(acc[t], h0, h1, h2_, h3, b0, b1);
                    mma_tf32(acc[t], l0, l1, l2, l3, b0, b1);
                }
            } else {
                #pragma unroll
                for (int t = 0; t < 4; t++) {
                    int n0 = (colbase + t * 8 + g2) * AP + kc;
                    uint32_t b0 = wt[n0 + cq];
                    uint32_t b1 = wt[n0 + cq + 4];
                    mma_tf32(acc[t], h0, h1, h2_, h3, b0, b1);
                }
            }
        }

        if (s == 0) {
            #pragma unroll
            for (int t = 0; t < 4; t++)
                #pragma unroll
                for (int e = 0; e < 4; e++) acc[t][e] *= 0.17677669529663687f;
        }
        if (s == 3) {
            #pragma unroll
            for (int t = 0; t < 4; t++) {
                int col = colbase + t * 8 + cq * 2;
                float2 bgv = __ldg((const float2*)&bg[col]);
                acc[t][0] = 1.f / (1.f + __expf(-(acc[t][0] + bgv.x)));
                acc[t][1] = 1.f / (1.f + __expf(-(acc[t][1] + bgv.y)));
                acc[t][2] = 1.f / (1.f + __expf(-(acc[t][2] + bgv.x)));
                acc[t][3] = 1.f / (1.f + __expf(-(acc[t][3] + bgv.y)));
            }
        }
        float* dst = (s == 0) ? g_q : (s == 1) ? g_k : (s == 2) ? g_v : g_gate;
        #pragma unroll
        for (int t = 0; t < 4; t++) {
            int col = colbase + t * 8 + cq * 2;
            int h = col >> 5, d = col & 31;
            *(float2*)&dst[(((size_t)i0 * NH + h) * NRES + j0) * DH + d] =
                make_float2(acc[t][0], acc[t][1]);
            *(float2*)&dst[(((size_t)i1 * NH + h) * NRES + j1) * DH + d] =
                make_float2(acc[t][2], acc[t][3]);
        }
        __syncthreads();
    }
}

// =====================================================================
// Kernel B: attention per (i,h), tf32 mma, 256 thr (R9 structure:
// smem P staging), Q fragments direct from global (verified in R10).
// =====================================================================
#define KS_OFF    0
#define VS_OFF    (KS_OFF + 320*36)
#define PS_OFF    (VS_OFF + 320*36)            // 8 warps x [16][164]
#define MSK_OFF   (PS_OFF + 8*16*164)
#define RED_OFF   (MSK_OFF + 320)              // 8 warps x 16 rows x {m,s}
#define OPART_OFF (RED_OFF + 8*16*2)           // 4 pairs x [16][32]
#define SMEM_B    ((OPART_OFF + 4*16*32) * 4)

__global__ __launch_bounds__(256, 1) void kB(const float* __restrict__ mask)
{
    extern __shared__ float sm[];
    uint32_t* ksu = (uint32_t*)(sm + KS_OFF);
    uint32_t* vsu = (uint32_t*)(sm + VS_OFF);
    uint32_t* psu = (uint32_t*)(sm + PS_OFF);
    float* msk   = sm + MSK_OFF;
    float* red   = sm + RED_OFF;
    float* opart = sm + OPART_OFF;

    int i = blockIdx.x, h = blockIdx.y;
    int tid = threadIdx.x, lane = tid & 31, w = tid >> 5;
    int p2 = w >> 1, half = w & 1;
    int khalf = half * 160;
    int g = lane >> 2, c = lane & 3;

    size_t base = ((size_t)i * NH + h) * (NRES * DH);
    const float* kg = g_k    + base;
    const float* qg = g_q    + base;
    const float* vg = g_v    + base;
    const float* gg = g_gate + base;

    for (int idx = tid; idx < NRES * DH; idx += 256) {
        int kk = idx >> 5, d = idx & 31;
        ksu[kk * 36 + d] = f2tf(kg[idx]);
        vsu[kk * 36 + d] = f2tf(vg[idx]);
    }
    for (int idx = tid; idx < NRES; idx += 256)
        msk[idx] = 1.0e9f * (mask[(size_t)i * NRES + idx] - 1.f);

    const float* bias_h = g_bias + (size_t)h * NN;
    uint32_t* pw = psu + w * 16 * 164;

    __syncthreads();

    #pragma unroll 1
    for (int p = 0; p < 5; p++) {
        int qbase = p * 64 + p2 * 16;

        // ---- S = Q_tile x K_half^T : Q fragments direct from global ----
        float s[20][4];
        #pragma unroll
        for (int t = 0; t < 20; t++)
            #pragma unroll
            for (int e = 0; e < 4; e++) s[t][e] = 0.f;

        #pragma unroll
        for (int ds = 0; ds < 4; ds++) {
            int dc = ds * 8;
            const float* q0 = &qg[(qbase + g) * DH + dc];
            const float* q1 = &qg[(qbase + g + 8) * DH + dc];
            uint32_t a0 = f2tf(__ldg(q0 + c));
            uint32_t a1 = f2tf(__ldg(q1 + c));
            uint32_t a2 = f2tf(__ldg(q0 + c + 4));
            uint32_t a3 = f2tf(__ldg(q1 + c + 4));
            #pragma unroll
            for (int t = 0; t < 20; t++) {
                int n0 = (khalf + t * 8 + g) * 36 + dc;
                uint32_t b0 = ksu[n0 + c];
                uint32_t b1 = ksu[n0 + c + 4];
                mma_tf32(s[t], a0, a1, a2, a3, b0, b1);
            }
        }

        int row0 = qbase + g, row1 = row0 + 8;
        #pragma unroll
        for (int t = 0; t < 20; t++) {
            int col = khalf + t * 8 + c * 2;
            float2 mk = *(const float2*)&msk[col];
            float2 bA = __ldg((const float2*)&bias_h[(size_t)row0 * NRES + col]);
            float2 bB = __ldg((const float2*)&bias_h[(size_t)row1 * NRES + col]);
            s[t][0] += bA.x + mk.x;  s[t][1] += bA.y + mk.y;
            s[t][2] += bB.x + mk.x;  s[t][3] += bB.y + mk.y;
        }

        // ---- local softmax over 160 ----
        float mA = -1e30f, mB = -1e30f;
        #pragma unroll
        for (int t = 0; t < 20; t++) {
            mA = fmaxf(mA, fmaxf(s[t][0], s[t][1]));
            mB = fmaxf(mB, fmaxf(s[t][2], s[t][3]));
        }
        mA = fmaxf(mA, __shfl_xor_sync(0xffffffffu, mA, 1));
        mB = fmaxf(mB, __shfl_xor_sync(0xffffffffu, mB, 1));
        mA = fmaxf(mA, __shfl_xor_sync(0xffffffffu, mA, 2));
        mB = fmaxf(mB, __shfl_xor_sync(0xffffffffu, mB, 2));

        float sA = 0.f, sB = 0.f;
        #pragma unroll
        for (int t = 0; t < 20; t++) {
            s[t][0] = __expf(s[t][0] - mA); sA += s[t][0];
            s[t][1] = __expf(s[t][1] - mA); sA += s[t][1];
            s[t][2] = __expf(s[t][2] - mB); sB += s[t][2];
            s[t][3] = __expf(s[t][3] - mB); sB += s[t][3];
        }
        sA += __shfl_xor_sync(0xffffffffu, sA, 1);
        sB += __shfl_xor_sync(0xffffffffu, sB, 1);
        sA += __shfl_xor_sync(0xffffffffu, sA, 2);
        sB += __shfl_xor_sync(0xffffffffu, sB, 2);

        if (c == 0) {
            red[(w * 16 + g)     * 2]     = mA;
            red[(w * 16 + g)     * 2 + 1] = sA;
            red[(w * 16 + g + 8) * 2]     = mB;
            red[(w * 16 + g + 8) * 2 + 1] = sB;
        }
        __syncthreads();

        // ---- merge with partner half ----
        int wo = w ^ 1;
        float moA = red[(wo * 16 + g) * 2],     soA = red[(wo * 16 + g) * 2 + 1];
        float moB = red[(wo * 16 + g + 8) * 2], soB = red[(wo * 16 + g + 8) * 2 + 1];
        float MA = fmaxf(mA, moA), MB = fmaxf(mB, moB);
        float eA = __expf(mA - MA), eB = __expf(mB - MB);
        float facA = eA / (sA * eA + soA * __expf(moA - MA));
        float facB = eB / (sB * eB + soB * __expf(moB - MB));

        // ---- P (scaled, tf32) to per-warp smem ----
        #pragma unroll
        for (int t = 0; t < 20; t++) {
            int kl = t * 8 + c * 2;
            uint32_t p0 = f2tf(s[t][0] * facA);
            uint32_t p1 = f2tf(s[t][1] * facA);
            uint32_t p2_ = f2tf(s[t][2] * facB);
            uint32_t p3 = f2tf(s[t][3] * facB);
            *(uint2*)&pw[g * 164 + kl]       = make_uint2(p0, p1);
            *(uint2*)&pw[(g + 8) * 164 + kl] = make_uint2(p2_, p3);
        }
        __syncwarp();

        // ---- O = P x V_half ----
        float o[4][4];
        #pragma unroll
        for (int t = 0; t < 4; t++)
            #pragma unroll
            for (int e = 0; e < 4; e++) o[t][e] = 0.f;

        #pragma unroll 4
        for (int ks = 0; ks < 20; ks++) {
            int kc = ks * 8;
            uint32_t a0 = pw[g * 164 + kc + c];
            uint32_t a1 = pw[(g + 8) * 164 + kc + c];
            uint32_t a2 = pw[g * 164 + kc + c + 4];
            uint32_t a3 = pw[(g + 8) * 164 + kc + c + 4];
            int vr0 = (khalf + kc + c) * 36;
            int vr1 = (khalf + kc + c + 4) * 36;
            #pragma unroll
            for (int t = 0; t < 4; t++) {
                uint32_t b0 = vsu[vr0 + t * 8 + g];
                uint32_t b1 = vsu[vr1 + t * 8 + g];
                mma_tf32(o[t], a0, a1, a2, a3, b0, b1);
            }
        }

        // ---- pair merge + gate + store ----
        if (half) {
            #pragma unroll
            for (int t = 0; t < 4; t++) {
                int col = t * 8 + c * 2;
                *(float2*)&opart[(p2 * 16 + g) * 32 + col]     = make_float2(o[t][0], o[t][1]);
                *(float2*)&opart[(p2 * 16 + g + 8) * 32 + col] = make_float2(o[t][2], o[t][3]);
            }
        }
        __syncthreads();
        if (!half) {
            #pragma unroll
            for (int t = 0; t < 4; t++) {
                int col = t * 8 + c * 2;
                float2 qa = *(const float2*)&opart[(p2 * 16 + g) * 32 + col];
                float2 qb = *(const float2*)&opart[(p2 * 16 + g + 8) * 32 + col];
                float2 gA = __ldg((const float2*)&gg[row0 * 32 + col]);
                float2 gB = __ldg((const float2*)&gg[row1 * 32 + col]);
                float2 rA = make_float2((o[t][0] + qa.x) * gA.x, (o[t][1] + qa.y) * gA.y);
                float2 rB = make_float2((o[t][2] + qb.x) * gB.x, (o[t][3] + qb.y) * gB.y);
                *(float2*)&g_og[((size_t)i * NRES + row0) * CDIM + h * DH + col] = rA;
                *(float2*)&g_og[((size_t)i * NRES + row1) * CDIM + h * DH + col] = rB;
            }
        }
        __syncthreads();
    }
}

// =====================================================================
// Kernel C (tensor, 1024 thr): out = og @ wo + bo. (unchanged)
// =====================================================================
#define KC_A  0
#define KC_WT (KC_A + 128*AP)
#define SMEM_C ((KC_WT + 128*AP) * 4)

__global__ __launch_bounds__(1024, 1) void kC(
    const float* __restrict__ bo, float* __restrict__ out)
{
    extern __shared__ float sm[];
    uint32_t* ao = (uint32_t*)(sm + KC_A);
    uint32_t* wt = (uint32_t*)(sm + KC_WT);

    int tid = threadIdx.x, lane = tid & 31, w = tid >> 5;
    int g2 = lane >> 2, cq = lane & 3;
    int rw = w & 7, nc = w >> 3;
    int colbase = nc * 32;
    int Rb = blockIdx.x * 128;

    const uint4* wsrc = (const uint4*)(g_wt + 4 * 16384);
    const float4* asrc = (const float4*)(g_og + (size_t)Rb * CDIM);
    #pragma unroll
    for (int i = 0; i < 4; i++) {
        int idx4 = tid + i * 1024;
        int n = idx4 >> 5, k4 = idx4 & 31;
        uint4 wv = __ldg(&wsrc[idx4]);
        *(uint4*)&wt[n * AP + k4 * 4] = wv;
        float4 av = asrc[idx4];
        uint4 at;
        at.x = f2tf(av.x); at.y = f2tf(av.y); at.z = f2tf(av.z); at.w = f2tf(av.w);
        *(uint4*)&ao[n * AP + k4 * 4] = at;
    }
    __syncthreads();

    int r0 = (rw << 4) + g2;

    float acc[4][4];
    #pragma unroll
    for (int t = 0; t < 4; t++)
        #pragma unroll
        for (int e = 0; e < 4; e++) acc[t][e] = 0.f;

    #pragma unroll 4
    for (int ks = 0; ks < 16; ks++) {
        int kc = ks * 8;
        uint32_t a0 = ao[r0 * AP + kc + cq];
        uint32_t a1 = ao[(r0 + 8) * AP + kc + cq];
        uint32_t a2 = ao[r0 * AP + kc + cq + 4];
        uint32_t a3 = ao[(r0 + 8) * AP + kc + cq + 4];
        #pragma unroll
        for (int t = 0; t < 4; t++) {
            int n0 = (colbase + t * 8 + g2) * AP + kc;
            uint32_t b0 = wt[n0 + cq];
            uint32_t b1 = wt[n0 + cq + 4];
            mma_tf32(acc[t], a0, a1, a2, a3, b0, b1);
        }
    }

    #pragma unroll
    for (int t = 0; t < 4; t++) {
        int col = colbase + t * 8 + cq * 2;
        float2 bb = __ldg((const float2*)&bo[col]);
        *(float2*)&out[(size_t)(Rb + r0) * CDIM + col] =
            make_float2(acc[t][0] + bb.x, acc[t][1] + bb.y);
        *(float2*)&out[(size_t)(Rb + r0 + 8) * CDIM + col] =
            make_float2(acc[t][2] + bb.x, acc[t][3] + bb.y);
    }
}

// =====================================================================
extern "C" void kernel_launch(void* const* d_in, const int* in_sizes, int n_in,
                              void* d_out, int out_size)
{
    const float* x    = (const float*)d_in[0];
    const float* mask = (const float*)d_in[1];
    const float* lng  = (const float*)d_in[2];
    const float* lnb  = (const float*)d_in[3];
    const float* wb   = (const float*)d_in[4];
    const float* wq   = (const float*)d_in[5];
    const float* wk   = (const float*)d_in[6];
    const float* wv   = (const float*)d_in[7];
    const float* wg   = (const float*)d_in[8];
    const float* bg   = (const float*)d_in[9];
    const float* wo   = (const float*)d_in[10];
    const float* bo   = (const float*)d_in[11];
    float* out = (float*)d_out;

    cudaFuncSetAttribute(kA, cudaFuncAttributeMaxDynamicSharedMemorySize, SMEM_A);
    cudaFuncSetAttribute(kB, cudaFuncAttributeMaxDynamicSharedMemorySize, SMEM_B);
    cudaFuncSetAttribute(kC, cudaFuncAttributeMaxDynamicSharedMemorySize, SMEM_C);

    kW<<<320, 256>>>(wq, wk, wv, wg, wo);
    kA<<<NN / 128, 1024, SMEM_A>>>(x, lng, lnb, wb, bg);
    kB<<<dim3(NRES, NH), 256, SMEM_B>>>(mask);
    kC<<<NN / 128, 1024, SMEM_C>>>(bo, out);
}